// round 5
// baseline (speedup 1.0000x reference)
#include <cuda_runtime.h>
#include <cstdint>
#include <cstddef>

// MeanAggregator on GB300 (sm_103a; ptxas target sm_103 -> legacy tf32 mma.sync).
//
//   out[:, 0:64]   = self_x @ Ws + bs                       (prep kernel)
//   out[:, 64:128] = (adj @ (nx @ Wn)) / max(rowsum(adj),1) + bn
//     -> one tf32 GEMM: D[16384,72] = adj @ B^T
//        B[72,16384] = [ (nx@Wn)^T ; ones ; zeros(7) ]; D col 64 = deg.
//
// Fragment-ordered layouts: within each 32-k chunk, element at k-offset c sits
// at position p = (c&3)*8 + (c>>2), so thread (g,tig) of an mma group reads its
// 8 per-row fragment values as two contiguous float4s -> LDS.128 only.
//   A: permuted during cp.async (4B scatter).  B: pre-permuted in gmem by prep.

#define NROWS    16384
#define KC       32
#define NIT      (NROWS / KC)            // 512
#define RSTRIDE  36                      // floats per smem row (32 + 4 pad)
#define A_ROWS   128
#define B_ROWS   72
#define A_ST_BYTES (A_ROWS * RSTRIDE * 4)            // 18432
#define B_ST_BYTES (B_ROWS * RSTRIDE * 4)            // 10368
#define ST_BYTES   (A_ST_BYTES + B_ST_BYTES)         // 28800
#define SMEM_TOTAL (256 + 4 * ST_BYTES)              // 115456

__device__ float g_B[(size_t)B_ROWS * NROWS];        // 4.5 MB static scratch

// ---------------- helpers ----------------

static __device__ __forceinline__ uint32_t smem_u32(const void* p) {
    uint32_t a;
    asm("{ .reg .u64 t; cvta.to.shared.u64 t, %1; cvt.u32.u64 %0, t; }"
        : "=r"(a) : "l"(p));
    return a;
}

static __device__ __forceinline__ void cp16(uint32_t dst, const void* src) {
    asm volatile("cp.async.cg.shared.global [%0], [%1], 16;"
                 :: "r"(dst), "l"(src) : "memory");
}

static __device__ __forceinline__ void cp4(uint32_t dst, const void* src) {
    asm volatile("cp.async.ca.shared.global [%0], [%1], 4;"
                 :: "r"(dst), "l"(src) : "memory");
}

static __device__ __forceinline__ void mma_tf32(float* d,
                                                uint32_t a0, uint32_t a1,
                                                uint32_t a2, uint32_t a3,
                                                uint32_t b0, uint32_t b1) {
    asm volatile(
        "mma.sync.aligned.m16n8k8.row.col.f32.tf32.tf32.f32 "
        "{%0,%1,%2,%3}, {%4,%5,%6,%7}, {%8,%9}, {%0,%1,%2,%3};"
        : "+f"(d[0]), "+f"(d[1]), "+f"(d[2]), "+f"(d[3])
        : "r"(a0), "r"(a1), "r"(a2), "r"(a3), "r"(b0), "r"(b1));
}

// ---------------- stage loader ----------------

static __device__ __forceinline__ void load_stage(char* smem, int slot, int k0,
                                                  int m0, int tid,
                                                  const float* __restrict__ adj) {
    char* base = smem + 256 + slot * ST_BYTES;
    // A: 128 rows x 32 cols, permuted 4B scatter. Thread -> (row0 = tid>>5, c = tid&31),
    // then strides 8 rows per step. Gmem side: lanes cover c=0..31 -> one 128B line.
    {
        const int c  = tid & 31;
        const int r0 = tid >> 5;
        const int p  = (c & 3) * 8 + (c >> 2);
        const float* src = adj + (size_t)(m0 + r0) * NROWS + k0 + c;
        const uint32_t dst0 = smem_u32(base + r0 * (RSTRIDE * 4) + p * 4);
#pragma unroll
        for (int i = 0; i < 16; i++)
            cp4(dst0 + i * 8 * (RSTRIDE * 4), src + (size_t)i * 8 * NROWS);
    }
    // B: already fragment-ordered in gmem; 16B chunks. 72 rows x 8 chunks = 576.
#pragma unroll
    for (int i = 0; i < 3; i++) {
        const int cb = i * 256 + tid;
        if (cb < 576) {
            const int row = cb >> 3, j = cb & 7;
            cp16(smem_u32(base + A_ST_BYTES + row * (RSTRIDE * 4) + j * 16),
                 g_B + (size_t)row * NROWS + k0 + j * 4);
        }
    }
}

// ---------------- main GEMM ----------------

__global__ void __launch_bounds__(256, 1)
gcn_gemm(const float* __restrict__ adj, const float* __restrict__ nbias,
         float* __restrict__ out) {
    extern __shared__ char smem[];
    const int tid  = threadIdx.x;
    const int lane = tid & 31;
    const int warp = tid >> 5;
    const int mw   = warp >> 1;             // m-strip 0..3 (32 rows)
    const int nh   = warp & 1;              // n-half 0/1
    const int rm   = mw * 32;
    const int g    = lane >> 2;
    const int tig  = lane & 3;
    const int m0   = blockIdx.x * 128;

    if (tid < 64) ((float*)smem)[tid] = nbias[tid];

    load_stage(smem, 0, 0,      m0, tid, adj);
    asm volatile("cp.async.commit_group;" ::: "memory");
    load_stage(smem, 1, KC,     m0, tid, adj);
    asm volatile("cp.async.commit_group;" ::: "memory");
    load_stage(smem, 2, 2 * KC, m0, tid, adj);
    asm volatile("cp.async.commit_group;" ::: "memory");

    int toff[5];
#pragma unroll
    for (int nt = 0; nt < 4; nt++) toff[nt] = nh * 32 + nt * 8;
    toff[4] = 64;

    float acc[2][5][4];
#pragma unroll
    for (int mt = 0; mt < 2; mt++)
#pragma unroll
        for (int nt = 0; nt < 5; nt++)
#pragma unroll
            for (int q = 0; q < 4; q++) acc[mt][nt][q] = 0.0f;

    for (int it = 0; it < NIT; it++) {
        asm volatile("cp.async.wait_group 2;" ::: "memory");
        __syncthreads();

        const int ld = it + 3;
        if (ld < NIT) load_stage(smem, ld & 3, ld * KC, m0, tid, adj);
        asm volatile("cp.async.commit_group;" ::: "memory");

        const uint32_t* base = (const uint32_t*)(smem + 256 + (it & 3) * ST_BYTES);
        const uint32_t* Ap = base + (rm + g) * RSTRIDE + tig * 8;
        const uint32_t* Bp = base + A_ROWS * RSTRIDE + g * RSTRIDE + tig * 8;

        uint4 Ar[4][2];                     // rows g, g+8, g+16, g+24
#pragma unroll
        for (int r = 0; r < 4; r++) {
            Ar[r][0] = *reinterpret_cast<const uint4*>(Ap + r * 8 * RSTRIDE);
            Ar[r][1] = *reinterpret_cast<const uint4*>(Ap + r * 8 * RSTRIDE + 4);
        }
        uint4 Br[5][2];
#pragma unroll
        for (int t = 0; t < 5; t++) {
            Br[t][0] = *reinterpret_cast<const uint4*>(Bp + toff[t] * RSTRIDE);
            Br[t][1] = *reinterpret_cast<const uint4*>(Bp + toff[t] * RSTRIDE + 4);
        }

#pragma unroll
        for (int kk = 0; kk < 4; kk++) {
            const int h = kk >> 1;
            const int q = (kk & 1) * 2;
            const uint32_t* a0p = reinterpret_cast<const uint32_t*>(&Ar[0][h]);
            const uint32_t* a1p = reinterpret_cast<const uint32_t*>(&Ar[1][h]);
            const uint32_t* a2p = reinterpret_cast<const uint32_t*>(&Ar[2][h]);
            const uint32_t* a3p = reinterpret_cast<const uint32_t*>(&Ar[3][h]);
#pragma unroll
            for (int nt = 0; nt < 5; nt++) {
                const uint32_t* bp = reinterpret_cast<const uint32_t*>(&Br[nt][h]);
                mma_tf32(acc[0][nt], a0p[q], a1p[q], a0p[q + 1], a1p[q + 1],
                         bp[q], bp[q + 1]);
                mma_tf32(acc[1][nt], a2p[q], a3p[q], a2p[q + 1], a3p[q + 1],
                         bp[q], bp[q + 1]);
            }
        }
    }

    // ---- epilogue: deg from tile 4 (D col 64) ----
    const float* sb = (const float*)smem;
#pragma unroll
    for (int mt = 0; mt < 2; mt++) {
        const float d0 = __shfl_sync(0xffffffffu, acc[mt][4][0], lane & ~3);
        const float d1 = __shfl_sync(0xffffffffu, acc[mt][4][2], lane & ~3);
        const float inv0 = 1.0f / fmaxf(d0, 1.0f);
        const float inv1 = 1.0f / fmaxf(d1, 1.0f);
        const int r0 = m0 + rm + mt * 16 + g;
        float* o0 = out + (size_t)r0 * 128 + 64;
        float* o1 = out + (size_t)(r0 + 8) * 128 + 64;
#pragma unroll
        for (int nt = 0; nt < 4; nt++) {
            const int dcol = nh * 32 + nt * 8 + tig * 2;
            float2 v0, v1;
            v0.x = acc[mt][nt][0] * inv0 + sb[dcol];
            v0.y = acc[mt][nt][1] * inv0 + sb[dcol + 1];
            v1.x = acc[mt][nt][2] * inv1 + sb[dcol];
            v1.y = acc[mt][nt][3] * inv1 + sb[dcol + 1];
            *reinterpret_cast<float2*>(o0 + dcol) = v0;
            *reinterpret_cast<float2*>(o1 + dcol) = v1;
        }
    }
}

// ---------------- prep: out_self + fragment-ordered B ----------------

static __device__ __forceinline__ float to_tf32(float x) {
    uint32_t t;
    asm("cvt.rna.tf32.f32 %0, %1;" : "=r"(t) : "f"(x));
    return __uint_as_float(t);
}

static __device__ __forceinline__ float dot64(const float4* __restrict__ x,
                                              const float4* __restrict__ w) {
    float4 s = make_float4(0.f, 0.f, 0.f, 0.f);
#pragma unroll
    for (int i = 0; i < 16; i++) {
        const float4 wv = w[i];
        s.x = fmaf(x[i].x, wv.x, s.x);
        s.y = fmaf(x[i].y, wv.y, s.y);
        s.z = fmaf(x[i].z, wv.z, s.z);
        s.w = fmaf(x[i].w, wv.w, s.w);
    }
    return (s.x + s.y) + (s.z + s.w);
}

__global__ void __launch_bounds__(128)
gcn_prep(const float* __restrict__ sx, const float* __restrict__ nx,
         const float* __restrict__ Ws, const float* __restrict__ Wn,
         const float* __restrict__ bs, float* __restrict__ out) {
    __shared__ float wsT[64 * 64];
    __shared__ float wnT[64 * 64];
    __shared__ float sbias[64];
    const int tid = threadIdx.x;
    for (int i = tid; i < 4096; i += 128) {
        const int d = i >> 6, n = i & 63;
        wsT[n * 64 + d] = Ws[i];
        wnT[n * 64 + d] = Wn[i];
    }
    if (tid < 64) sbias[tid] = bs[tid];
    __syncthreads();

    const int m = blockIdx.x * 128 + tid;
    // fragment-ordered column index for this m (within its 32-chunk)
    const int c = m & 31;
    const size_t col = (size_t)(m & ~31) + (c & 3) * 8 + (c >> 2);
    {
        float4 x[16];
        const float4* xp = reinterpret_cast<const float4*>(sx + (size_t)m * 64);
#pragma unroll
        for (int i = 0; i < 16; i++) x[i] = xp[i];
        float* op = out + (size_t)m * 128;
        for (int n = 0; n < 64; n++)
            op[n] = dot64(x, reinterpret_cast<const float4*>(wsT + n * 64)) + sbias[n];
    }
    {
        float4 x[16];
        const float4* xp = reinterpret_cast<const float4*>(nx + (size_t)m * 64);
#pragma unroll
        for (int i = 0; i < 16; i++) x[i] = xp[i];
        for (int n = 0; n < 64; n++)
            g_B[(size_t)n * NROWS + col] =
                to_tf32(dot64(x, reinterpret_cast<const float4*>(wnT + n * 64)));
        g_B[(size_t)64 * NROWS + col] = 1.0f;
#pragma unroll
        for (int r = 65; r < 72; r++) g_B[(size_t)r * NROWS + col] = 0.0f;
    }
}

// ---------------- launch ----------------

extern "C" void kernel_launch(void* const* d_in, const int* in_sizes, int n_in,
                              void* d_out, int out_size) {
    const float* sx  = (const float*)d_in[0];
    const float* nx  = (const float*)d_in[1];
    const float* adj = (const float*)d_in[2];
    const float* Ws  = (const float*)d_in[3];
    const float* Wn  = (const float*)d_in[4];
    const float* bs  = (const float*)d_in[5];
    const float* bn  = (const float*)d_in[6];
    float* out = (float*)d_out;

    cudaFuncSetAttribute(gcn_gemm, cudaFuncAttributeMaxDynamicSharedMemorySize,
                         SMEM_TOTAL);
    gcn_prep<<<NROWS / 128, 128>>>(sx, nx, Ws, Wn, bs, out);
    gcn_gemm<<<NROWS / 128, 256, SMEM_TOTAL>>>(adj, bn, out);
}

// round 6
// speedup vs baseline: 1.3022x; 1.3022x over previous
#include <cuda_runtime.h>
#include <cstdint>
#include <cstddef>

// MeanAggregator on GB300 (sm_103a; ptxas target sm_103 -> legacy tf32 mma.sync).
//
//   out[:, 0:64]   = self_x @ Ws + bs                       (prep kernel)
//   out[:, 64:128] = (adj @ (nx @ Wn)) / max(rowsum(adj),1) + bn
//     -> one tf32 GEMM: D[16384,72] = adj @ B^T
//        B[72,16384] = [ (nx@Wn)^T ; ones ; zeros(7) ]; D col 64 = deg.
//
// R5: 64-row CTA tiles, 128 thr, 256 CTAs, 2 CTAs/SM (occupancy was the wall).
// A: plain layout, cp16 loader, scalar LDS (R3 pattern).
// B: fragment-ordered in gmem (prep permutes), uint4 LDS (R4 pattern).

#define NROWS    16384
#define KC       32
#define NIT      (NROWS / KC)            // 512
#define RSTRIDE  36                      // floats per smem row (32 + 4 pad)
#define A_ROWS   64
#define B_ROWS   72
#define A_ST_BYTES (A_ROWS * RSTRIDE * 4)            // 9216
#define B_ST_BYTES (B_ROWS * RSTRIDE * 4)            // 10368
#define ST_BYTES   (A_ST_BYTES + B_ST_BYTES)         // 19584
#define SMEM_TOTAL (256 + 4 * ST_BYTES)              // 78592+256 = 78592? -> 78592
                                                     // (256 + 78336 = 78592)

__device__ float g_B[(size_t)B_ROWS * NROWS];        // 4.5 MB static scratch

// ---------------- helpers ----------------

static __device__ __forceinline__ uint32_t smem_u32(const void* p) {
    uint32_t a;
    asm("{ .reg .u64 t; cvta.to.shared.u64 t, %1; cvt.u32.u64 %0, t; }"
        : "=r"(a) : "l"(p));
    return a;
}

static __device__ __forceinline__ void cp16(uint32_t dst, const void* src) {
    asm volatile("cp.async.cg.shared.global [%0], [%1], 16;"
                 :: "r"(dst), "l"(src) : "memory");
}

static __device__ __forceinline__ void mma_tf32(float* d,
                                                uint32_t a0, uint32_t a1,
                                                uint32_t a2, uint32_t a3,
                                                uint32_t b0, uint32_t b1) {
    asm volatile(
        "mma.sync.aligned.m16n8k8.row.col.f32.tf32.tf32.f32 "
        "{%0,%1,%2,%3}, {%4,%5,%6,%7}, {%8,%9}, {%0,%1,%2,%3};"
        : "+f"(d[0]), "+f"(d[1]), "+f"(d[2]), "+f"(d[3])
        : "r"(a0), "r"(a1), "r"(a2), "r"(a3), "r"(b0), "r"(b1));
}

// ---------------- stage loader (cp16, plain A + fragment-ordered B) -----------

static __device__ __forceinline__ void load_stage(char* smem, int slot, int k0,
                                                  int m0, int tid,
                                                  const float* __restrict__ adj) {
    char* base = smem + 256 + slot * ST_BYTES;
    // A: 64 rows x 8 chunks (16B) = 512; B: 72 rows x 8 chunks = 576. Total 1088.
#pragma unroll
    for (int i = 0; i < 9; i++) {
        const int c = i * 128 + tid;
        if (c < 512) {
            const int row = c >> 3, w = c & 7;
            cp16(smem_u32(base + row * (RSTRIDE * 4) + w * 16),
                 adj + (size_t)(m0 + row) * NROWS + k0 + w * 4);
        } else if (c < 1088) {
            const int cb = c - 512;
            const int row = cb >> 3, j = cb & 7;
            cp16(smem_u32(base + A_ST_BYTES + row * (RSTRIDE * 4) + j * 16),
                 g_B + (size_t)row * NROWS + k0 + j * 4);
        }
    }
}

// ---------------- main GEMM ----------------

__global__ void __launch_bounds__(128, 2)
gcn_gemm(const float* __restrict__ adj, const float* __restrict__ nbias,
         float* __restrict__ out) {
    extern __shared__ char smem[];
    const int tid  = threadIdx.x;
    const int lane = tid & 31;
    const int warp = tid >> 5;               // 0..3
    const int mw   = warp >> 1;              // m-strip 0/1 (32 rows each)
    const int nh   = warp & 1;               // n-half 0/1
    const int rm   = mw * 32;
    const int g    = lane >> 2;
    const int tig  = lane & 3;
    const int m0   = blockIdx.x * 64;

    if (tid < 64) ((float*)smem)[tid] = nbias[tid];

    load_stage(smem, 0, 0,      m0, tid, adj);
    asm volatile("cp.async.commit_group;" ::: "memory");
    load_stage(smem, 1, KC,     m0, tid, adj);
    asm volatile("cp.async.commit_group;" ::: "memory");
    load_stage(smem, 2, 2 * KC, m0, tid, adj);
    asm volatile("cp.async.commit_group;" ::: "memory");

    int toff[5];
#pragma unroll
    for (int nt = 0; nt < 4; nt++) toff[nt] = nh * 32 + nt * 8;
    toff[4] = 64;

    float acc[2][5][4];
#pragma unroll
    for (int mt = 0; mt < 2; mt++)
#pragma unroll
        for (int nt = 0; nt < 5; nt++)
#pragma unroll
            for (int q = 0; q < 4; q++) acc[mt][nt][q] = 0.0f;

    for (int it = 0; it < NIT; it++) {
        asm volatile("cp.async.wait_group 2;" ::: "memory");
        __syncthreads();

        const int ld = it + 3;
        if (ld < NIT) load_stage(smem, ld & 3, ld * KC, m0, tid, adj);
        asm volatile("cp.async.commit_group;" ::: "memory");

        const uint32_t* base = (const uint32_t*)(smem + 256 + (it & 3) * ST_BYTES);
        const uint32_t* Ap = base + (rm + g) * RSTRIDE + tig;
        const uint32_t* Bp = base + A_ROWS * RSTRIDE + g * RSTRIDE + tig * 8;

        // B fragments: 10 x LDS.128 (fragment-ordered rows)
        uint4 Br[5][2];
#pragma unroll
        for (int t = 0; t < 5; t++) {
            Br[t][0] = *reinterpret_cast<const uint4*>(Bp + toff[t] * RSTRIDE);
            Br[t][1] = *reinterpret_cast<const uint4*>(Bp + toff[t] * RSTRIDE + 4);
        }

#pragma unroll
        for (int kk = 0; kk < 4; kk++) {
            const int ko = kk * 8;
            const uint32_t a0 = Ap[ko];
            const uint32_t a1 = Ap[ko + 8 * RSTRIDE];
            const uint32_t a2 = Ap[ko + 4];
            const uint32_t a3 = Ap[ko + 8 * RSTRIDE + 4];
            const uint32_t a4 = Ap[ko + 16 * RSTRIDE];
            const uint32_t a5 = Ap[ko + 24 * RSTRIDE];
            const uint32_t a6 = Ap[ko + 16 * RSTRIDE + 4];
            const uint32_t a7 = Ap[ko + 24 * RSTRIDE + 4];
            const int h = kk >> 1;
            const int q = (kk & 1) * 2;
#pragma unroll
            for (int nt = 0; nt < 5; nt++) {
                const uint32_t* bp = reinterpret_cast<const uint32_t*>(&Br[nt][h]);
                mma_tf32(acc[0][nt], a0, a1, a2, a3, bp[q], bp[q + 1]);
                mma_tf32(acc[1][nt], a4, a5, a6, a7, bp[q], bp[q + 1]);
            }
        }
    }

    // ---- epilogue: deg from tile 4 (D col 64) ----
    const float* sb = (const float*)smem;
#pragma unroll
    for (int mt = 0; mt < 2; mt++) {
        const float d0 = __shfl_sync(0xffffffffu, acc[mt][4][0], lane & ~3);
        const float d1 = __shfl_sync(0xffffffffu, acc[mt][4][2], lane & ~3);
        const float inv0 = 1.0f / fmaxf(d0, 1.0f);
        const float inv1 = 1.0f / fmaxf(d1, 1.0f);
        const int r0 = m0 + rm + mt * 16 + g;
        float* o0 = out + (size_t)r0 * 128 + 64;
        float* o1 = out + (size_t)(r0 + 8) * 128 + 64;
#pragma unroll
        for (int nt = 0; nt < 4; nt++) {
            const int dcol = nh * 32 + nt * 8 + tig * 2;
            float2 v0, v1;
            v0.x = acc[mt][nt][0] * inv0 + sb[dcol];
            v0.y = acc[mt][nt][1] * inv0 + sb[dcol + 1];
            v1.x = acc[mt][nt][2] * inv1 + sb[dcol];
            v1.y = acc[mt][nt][3] * inv1 + sb[dcol + 1];
            *reinterpret_cast<float2*>(o0 + dcol) = v0;
            *reinterpret_cast<float2*>(o1 + dcol) = v1;
        }
    }
}

// ---------------- prep: out_self + fragment-ordered B ----------------

static __device__ __forceinline__ float to_tf32(float x) {
    uint32_t t;
    asm("cvt.rna.tf32.f32 %0, %1;" : "=r"(t) : "f"(x));
    return __uint_as_float(t);
}

static __device__ __forceinline__ float dot64(const float4* __restrict__ x,
                                              const float4* __restrict__ w) {
    float4 s = make_float4(0.f, 0.f, 0.f, 0.f);
#pragma unroll
    for (int i = 0; i < 16; i++) {
        const float4 wv = w[i];
        s.x = fmaf(x[i].x, wv.x, s.x);
        s.y = fmaf(x[i].y, wv.y, s.y);
        s.z = fmaf(x[i].z, wv.z, s.z);
        s.w = fmaf(x[i].w, wv.w, s.w);
    }
    return (s.x + s.y) + (s.z + s.w);
}

__global__ void __launch_bounds__(128)
gcn_prep(const float* __restrict__ sx, const float* __restrict__ nx,
         const float* __restrict__ Ws, const float* __restrict__ Wn,
         const float* __restrict__ bs, float* __restrict__ out) {
    __shared__ float wsT[64 * 64];
    __shared__ float wnT[64 * 64];
    __shared__ float sbias[64];
    const int tid = threadIdx.x;
    for (int i = tid; i < 4096; i += 128) {
        const int d = i >> 6, n = i & 63;
        wsT[n * 64 + d] = Ws[i];
        wnT[n * 64 + d] = Wn[i];
    }
    if (tid < 64) sbias[tid] = bs[tid];
    __syncthreads();

    const int m = blockIdx.x * 128 + tid;
    const int c = m & 31;                     // fragment-ordered column
    const size_t col = (size_t)(m & ~31) + (c & 3) * 8 + (c >> 2);
    {
        float4 x[16];
        const float4* xp = reinterpret_cast<const float4*>(sx + (size_t)m * 64);
#pragma unroll
        for (int i = 0; i < 16; i++) x[i] = xp[i];
        float* op = out + (size_t)m * 128;
        for (int n = 0; n < 64; n++)
            op[n] = dot64(x, reinterpret_cast<const float4*>(wsT + n * 64)) + sbias[n];
    }
    {
        float4 x[16];
        const float4* xp = reinterpret_cast<const float4*>(nx + (size_t)m * 64);
#pragma unroll
        for (int i = 0; i < 16; i++) x[i] = xp[i];
        for (int n = 0; n < 64; n++)
            g_B[(size_t)n * NROWS + col] =
                to_tf32(dot64(x, reinterpret_cast<const float4*>(wnT + n * 64)));
        g_B[(size_t)64 * NROWS + col] = 1.0f;
#pragma unroll
        for (int r = 65; r < 72; r++) g_B[(size_t)r * NROWS + col] = 0.0f;
    }
}

// ---------------- launch ----------------

extern "C" void kernel_launch(void* const* d_in, const int* in_sizes, int n_in,
                              void* d_out, int out_size) {
    const float* sx  = (const float*)d_in[0];
    const float* nx  = (const float*)d_in[1];
    const float* adj = (const float*)d_in[2];
    const float* Ws  = (const float*)d_in[3];
    const float* Wn  = (const float*)d_in[4];
    const float* bs  = (const float*)d_in[5];
    const float* bn  = (const float*)d_in[6];
    float* out = (float*)d_out;

    cudaFuncSetAttribute(gcn_gemm, cudaFuncAttributeMaxDynamicSharedMemorySize,
                         SMEM_TOTAL);
    gcn_prep<<<NROWS / 128, 128>>>(sx, nx, Ws, Wn, bs, out);
    gcn_gemm<<<NROWS / 64, 128, SMEM_TOTAL>>>(adj, bn, out);
}